// round 3
// baseline (speedup 1.0000x reference)
#include <cuda_runtime.h>
#include <math.h>

#define BB   128
#define TT   256
#define HH   1024
#define KG   256     /* HH/4 feature-groups */
#define NBLK 128
#define NJ   8       /* output cols per CTA */
#define NTH  1024
#define K4G  32      /* k4 steps per K-group (8 groups) */
#define RST  129     /* sred row stride (floats) */

typedef unsigned long long u64;

/* Scratch (static device globals; no runtime allocation). */
__device__ float4 g_pre0[(size_t)TT * KG * BB];   /* [t][j4][b] */
__device__ float4 g_h0buf[2][KG * BB];            /* layer-0 hidden, double buffered, [k4][b] */
__device__ float4 g_h1buf[2][KG * BB];            /* layer-1 hidden */
__device__ unsigned int g_cnt;                    /* grid barrier counter */

/* ---------------- packed fp32x2 helpers (FFMA2 path) ---------------- */
__device__ __forceinline__ u64 fma2(u64 a, u64 b, u64 c) {
    u64 d; asm("fma.rn.f32x2 %0, %1, %2, %3;" : "=l"(d) : "l"(a), "l"(b), "l"(c)); return d;
}
__device__ __forceinline__ u64 pack2(float x, float y) {
    u64 r; asm("mov.b64 %0, {%1, %2};" : "=l"(r) : "f"(x), "f"(y)); return r;
}
__device__ __forceinline__ float2 unpk(u64 v) {
    float2 f; asm("mov.b64 {%0, %1}, %2;" : "=f"(f.x), "=f"(f.y) : "l"(v)); return f;
}
__device__ __forceinline__ void ldcg2(const float4* p, u64& x, u64& y) {
    asm("ld.global.cg.v2.u64 {%0,%1}, [%2];" : "=l"(x), "=l"(y) : "l"(p));
}

/* ------------------------------------------------------------------ */
/* Kernel 1: pre0[t][j][b] = sum_k x[b][t][k]*Wi0[k][j] + bi0[j]       */
/* ------------------------------------------------------------------ */
__global__ __launch_bounds__(256) void pre_gemm(const float* __restrict__ x,
                                                const float* __restrict__ Wi,
                                                const float* __restrict__ bi)
{
    if (blockIdx.x == 0 && blockIdx.y == 0 && threadIdx.x == 0) g_cnt = 0u;

    __shared__ float  sA[32][129];
    __shared__ float4 sB[32 * 16];

    const int t     = blockIdx.y;
    const int jbase = blockIdx.x * 64;
    const int tid   = threadIdx.x;
    const int rid   = tid & 31;
    const int cid   = tid >> 5;

    u64 acc[4][4];
#pragma unroll
    for (int i = 0; i < 4; ++i)
#pragma unroll
        for (int j = 0; j < 4; ++j) acc[i][j] = 0ull;

    const int brow = tid >> 1;
    const int half = tid & 1;

    for (int k0 = 0; k0 < HH; k0 += 32) {
        __syncthreads();
        const float* xs = x + ((size_t)brow * TT + t) * HH + k0 + half * 16;
#pragma unroll
        for (int q = 0; q < 4; ++q) {
            float4 v = *(const float4*)(xs + 4 * q);
            int kk = half * 16 + 4 * q;
            sA[kk + 0][brow] = v.x; sA[kk + 1][brow] = v.y;
            sA[kk + 2][brow] = v.z; sA[kk + 3][brow] = v.w;
        }
#pragma unroll
        for (int q = 0; q < 2; ++q) {
            int idx = tid + 256 * q;
            int kk = idx >> 4, jf = idx & 15;
            sB[idx] = *(const float4*)(Wi + (size_t)(k0 + kk) * HH + jbase + 4 * jf);
        }
        __syncthreads();

#pragma unroll
        for (int kk = 0; kk < 32; ++kk) {
            float a0 = sA[kk][rid], a1 = sA[kk][rid + 32];
            float a2 = sA[kk][rid + 64], a3 = sA[kk][rid + 96];
            const ulonglong2* bp = (const ulonglong2*)&sB[kk * 16 + cid * 2];
            ulonglong2 bb0 = bp[0];
            ulonglong2 bb1 = bp[1];
            u64 ad0 = pack2(a0, a0), ad1 = pack2(a1, a1);
            u64 ad2 = pack2(a2, a2), ad3 = pack2(a3, a3);
            acc[0][0] = fma2(ad0, bb0.x, acc[0][0]); acc[0][1] = fma2(ad0, bb0.y, acc[0][1]);
            acc[0][2] = fma2(ad0, bb1.x, acc[0][2]); acc[0][3] = fma2(ad0, bb1.y, acc[0][3]);
            acc[1][0] = fma2(ad1, bb0.x, acc[1][0]); acc[1][1] = fma2(ad1, bb0.y, acc[1][1]);
            acc[1][2] = fma2(ad1, bb1.x, acc[1][2]); acc[1][3] = fma2(ad1, bb1.y, acc[1][3]);
            acc[2][0] = fma2(ad2, bb0.x, acc[2][0]); acc[2][1] = fma2(ad2, bb0.y, acc[2][1]);
            acc[2][2] = fma2(ad2, bb1.x, acc[2][2]); acc[2][3] = fma2(ad2, bb1.y, acc[2][3]);
            acc[3][0] = fma2(ad3, bb0.x, acc[3][0]); acc[3][1] = fma2(ad3, bb0.y, acc[3][1]);
            acc[3][2] = fma2(ad3, bb1.x, acc[3][2]); acc[3][3] = fma2(ad3, bb1.y, acc[3][3]);
        }
    }

    float biv[8];
#pragma unroll
    for (int j = 0; j < 8; ++j) biv[j] = __ldg(&bi[jbase + cid * 8 + j]);

    const int jg = (jbase + cid * 8) >> 2;
#pragma unroll
    for (int i = 0; i < 4; ++i) {
        int row = rid + 32 * i;
#pragma unroll
        for (int gq = 0; gq < 2; ++gq) {
            float2 u0 = unpk(acc[i][2 * gq]);
            float2 u1 = unpk(acc[i][2 * gq + 1]);
            float4 v;
            v.x = u0.x + biv[4 * gq + 0];
            v.y = u0.y + biv[4 * gq + 1];
            v.z = u1.x + biv[4 * gq + 2];
            v.w = u1.y + biv[4 * gq + 3];
            g_pre0[((size_t)t * KG + jg + gq) * BB + row] = v;
        }
    }
}

/* ------------------------------------------------------------------ */
__device__ __forceinline__ void grid_sync(unsigned int target)
{
    __syncthreads();
    if (threadIdx.x == 0) {
        __threadfence();
        atomicAdd(&g_cnt, 1u);
        while (*(volatile unsigned int*)&g_cnt < target) { }
        __threadfence();
    }
    __syncthreads();
}

/* sred layout: [(g*16 + i) * RST + slot]; i = 0..7 acc1, 8..15 acc0.
   Writes: lanes vary slot (consecutive) -> conflict-free. */
#define RIDX(i, g, s) (((g) * 16 + (i)) * RST + (s))

/* ------------------------------------------------------------------ */
/* Kernel 2: persistent weight-stationary RNN, FFMA2, 1024 threads.    */
/* thread = (K-group g of 8, batch row slot of 128), 1 row per thread. */
/* Fused loop: per k4 load A0 & A1, feed Wi1/Wh0/Wh1 together.         */
/* ------------------------------------------------------------------ */
__global__ __launch_bounds__(NTH, 1) void rnn_persist(const float* __restrict__ h0,
                                                      const float* __restrict__ Wi,
                                                      const float* __restrict__ bi,
                                                      const float* __restrict__ Wh,
                                                      const float* __restrict__ bh,
                                                      float* __restrict__ out)
{
    extern __shared__ float4 smem4[];
    float4* sWh0 = smem4;              /* [8 cols][256 k4] */
    float4* sWi1 = smem4 + 2048;
    float4* sWh1 = smem4 + 4096;
    float*  sred = (float*)(smem4 + 6144);          /* [8][16][RST] */
    float*  sdot = sred + 8 * 16 * RST;             /* [8][8] init dot */

    const int cta  = blockIdx.x;
    const int th   = threadIdx.x;
    const int g    = th >> 7;          /* K group 0..7 */
    const int slot = th & 127;         /* batch row */
    const int j0   = cta * NJ;

    /* final-pass mapping */
    const int frow = th >> 3;          /* 0..127 */
    const int col  = th & 7;           /* this CTA's col 0..7 */
    const int jg4  = (j0 + col) >> 2;
    const int cl   = col & 3;

    const float* Wi1g = Wi + (size_t)HH * HH;
    const float* Wh1g = Wh + (size_t)HH * HH;

    /* One-time: gather weight column slices into SMEM (float4 over k). */
    for (int idx = th; idx < 2048; idx += NTH) {
        int jl = idx >> 8, k4 = idx & 255;
        int j = j0 + jl;
        int kb = k4 * 4;
        sWh0[idx] = make_float4(Wh[(size_t)(kb + 0) * HH + j], Wh[(size_t)(kb + 1) * HH + j],
                                Wh[(size_t)(kb + 2) * HH + j], Wh[(size_t)(kb + 3) * HH + j]);
        sWi1[idx] = make_float4(Wi1g[(size_t)(kb + 0) * HH + j], Wi1g[(size_t)(kb + 1) * HH + j],
                                Wi1g[(size_t)(kb + 2) * HH + j], Wi1g[(size_t)(kb + 3) * HH + j]);
        sWh1[idx] = make_float4(Wh1g[(size_t)(kb + 0) * HH + j], Wh1g[(size_t)(kb + 1) * HH + j],
                                Wh1g[(size_t)(kb + 2) * HH + j], Wh1g[(size_t)(kb + 3) * HH + j]);
    }

    const float bs1 = __ldg(&bi[HH + j0 + col]) + __ldg(&bh[HH + j0 + col]);
    const float b0r = __ldg(&bh[j0 + col]);

    /* h1 init: CTA covers k4 in [2*cta, 2*cta+2). */
    for (int idx = th; idx < 2 * BB; idx += NTH) {
        int k4l = idx >> 7, b = idx & 127;
        g_h1buf[1][(2 * cta + k4l) * BB + b] = *(const float4*)(h0 + HH + 4 * (2 * cta + k4l));
    }
    __syncthreads();

    /* hn0[0] init: dot0[col] = h0_l0 @ Wh0 (shared over batch rows). */
    {
        u64 d[NJ];
#pragma unroll
        for (int jj = 0; jj < NJ; ++jj) d[jj] = 0ull;
        for (int kk = 0; kk < K4G; ++kk) {
            int off = g * K4G + kk;
            ulonglong2 a = *(const ulonglong2*)(h0 + 4 * off);
#pragma unroll
            for (int jj = 0; jj < NJ; ++jj) {
                ulonglong2 w = *(const ulonglong2*)&sWh0[jj * 256 + off];
                d[jj] = fma2(a.x, w.x, fma2(a.y, w.y, d[jj]));
            }
        }
        if (slot == 0) {
#pragma unroll
            for (int jj = 0; jj < NJ; ++jj) {
                float2 f = unpk(d[jj]);
                sdot[g * 8 + jj] = f.x + f.y;
            }
        }
        __syncthreads();
        float dv = 0.0f;
#pragma unroll
        for (int g2 = 0; g2 < 8; ++g2) dv += sdot[g2 * 8 + col];
        float pre = ((const float*)g_pre0)[((size_t)jg4 * BB + frow) * 4 + cl];
        ((float*)g_h0buf[0])[((size_t)jg4 * BB + frow) * 4 + cl] = tanhf(pre + dv + b0r);
    }

    unsigned int ph = 1;
    grid_sync(ph * NBLK); ++ph;

    for (int t = 0; t < TT; ++t) {
        const float4* p0 = g_h0buf[t & 1]       + (size_t)g * K4G * BB + slot;
        const float4* p1 = g_h1buf[(t + 1) & 1] + (size_t)g * K4G * BB + slot;

        u64 acc1[NJ], acc0[NJ];
#pragma unroll
        for (int jj = 0; jj < NJ; ++jj) { acc1[jj] = 0ull; acc0[jj] = 0ull; }

        /* Fused K loop: A0 feeds Wi1 (acc1) + Wh0 (acc0); A1 feeds Wh1 (acc1). */
        {
            u64 a0x, a0y, a1x, a1y;
            ldcg2(p0, a0x, a0y);
            ldcg2(p1, a1x, a1y);
#pragma unroll 2
            for (int kk = 0; kk < K4G; ++kk) {
                u64 c0x = a0x, c0y = a0y, c1x = a1x, c1y = a1y;
                if (kk + 1 < K4G) {
                    ldcg2(p0 + (kk + 1) * BB, a0x, a0y);
                    ldcg2(p1 + (kk + 1) * BB, a1x, a1y);
                }
                int off = g * K4G + kk;
#pragma unroll
                for (int jj = 0; jj < NJ; ++jj) {
                    ulonglong2 wi1 = *(const ulonglong2*)&sWi1[jj * 256 + off];
                    acc1[jj] = fma2(c0x, wi1.x, fma2(c0y, wi1.y, acc1[jj]));
                    ulonglong2 wh1 = *(const ulonglong2*)&sWh1[jj * 256 + off];
                    acc1[jj] = fma2(c1x, wh1.x, fma2(c1y, wh1.y, acc1[jj]));
                    ulonglong2 wh0 = *(const ulonglong2*)&sWh0[jj * 256 + off];
                    acc0[jj] = fma2(c0x, wh0.x, fma2(c0y, wh0.y, acc0[jj]));
                }
            }
        }

        /* Partials for the 8-way K-group reduction. */
#pragma unroll
        for (int jj = 0; jj < NJ; ++jj) {
            float2 v;
            v = unpk(acc1[jj]); sred[RIDX(jj,     g, slot)] = v.x + v.y;
            v = unpk(acc0[jj]); sred[RIDX(jj + 8, g, slot)] = v.x + v.y;
        }
        __syncthreads();

        /* Final pass: 1024 threads, one (row,col) scalar each. */
        {
            float s1 = 0.0f;
#pragma unroll
            for (int g2 = 0; g2 < 8; ++g2) s1 += sred[RIDX(col, g2, frow)];
            float y = tanhf(s1 + bs1);
            out[((size_t)frow * TT + t) * HH + j0 + col] = y;
            ((float*)g_h1buf[t & 1])[((size_t)jg4 * BB + frow) * 4 + cl] = y;

            if (t < TT - 1) {
                float s0 = 0.0f;
#pragma unroll
                for (int g2 = 0; g2 < 8; ++g2) s0 += sred[RIDX(col + 8, g2, frow)];
                float pre = ((const float*)g_pre0)[((size_t)((size_t)(t + 1) * KG + jg4) * BB + frow) * 4 + cl];
                ((float*)g_h0buf[(t + 1) & 1])[((size_t)jg4 * BB + frow) * 4 + cl] =
                    tanhf(s0 + pre + b0r);
            } else {
                float* hn = out + (size_t)BB * TT * HH;
                hn[(size_t)(frow * 2 + 1) * HH + j0 + col] = y;
                float l0 = __ldcg(&((const float*)g_h0buf[t & 1])[((size_t)jg4 * BB + frow) * 4 + cl]);
                hn[(size_t)(frow * 2) * HH + j0 + col] = l0;
            }
        }

        if (t < TT - 1) { grid_sync(ph * NBLK); ++ph; }
    }
}

/* ------------------------------------------------------------------ */
extern "C" void kernel_launch(void* const* d_in, const int* in_sizes, int n_in,
                              void* d_out, int out_size)
{
    const float* x  = (const float*)d_in[0];
    const float* h0 = (const float*)d_in[1];
    const float* Wi = (const float*)d_in[2];
    const float* bi = (const float*)d_in[3];
    const float* Wh = (const float*)d_in[4];
    const float* bh = (const float*)d_in[5];
    float* out = (float*)d_out;

    dim3 g2(16, 256);
    pre_gemm<<<g2, 256>>>(x, Wi, bi);

    size_t smem = 6144 * sizeof(float4) + (8 * 16 * RST + 64) * sizeof(float);  /* ~161 KB */
    cudaFuncSetAttribute(rnn_persist, cudaFuncAttributeMaxDynamicSharedMemorySize, (int)smem);
    rnn_persist<<<NBLK, NTH, smem>>>(h0, Wi, bi, Wh, bh, out);
}